// round 16
// baseline (speedup 1.0000x reference)
#include <cuda_runtime.h>
#include <cuda_fp16.h>

#define MPIF 3.14159265358979323846f

// ----------------------------------------------------------------------------
// FBP as banded GEMM on mma.sync (legacy-HMMA tensor rate ~68 T MAC/s — k_gemm
// measured at ~100% of that pipe; tcgen05 PTX unavailable via compute_103).
//   K1 k_filter : ramp conv of 16 base frames -> fp16 (odd-tap parity split).
//   K2 k_wbuild : per (tile tau, K-chunk ch) banded weight rows, 17 chunks
//       (wrap split). NEW: per-chunk band width K16 in {1..4} x16 computed
//       from the exact umin/umax window -> ~30% fewer MACs, same weights.
//   K3 k_gemm   : D[128 s,128 p] = sum_ch A[s,16*K16]*B^T, m16n8k16, fp32
//       accum, cp.async double-buffered, dynamic K per chunk.
// ----------------------------------------------------------------------------

static constexpr int NCH = 17;                   // K-chunks per tile

__device__ __half g_Fh[16 * 1024 * 128];         // filtered frames fp16, 4 MB
__device__ __half g_W16[128 * NCH * 128 * 64];   // weights [tau*17+ch][p][w], 34 MB
__device__ int    g_base[128 * NCH];             // band base col per (tau,ch)
__device__ int    g_kw[128 * NCH];               // band width /16 per (tau,ch)

// --------------------------- K1: filter (odd-tap) ----------------------------
__global__ __launch_bounds__(256) void k_filter(const float* __restrict__ feat) {
    __shared__ float2 h2o[64];
    __shared__ float  ps[8][128];
    int tid = threadIdx.x;
    if (tid < 64) {
        int n1 = 2 * tid + 1;
        float s1 = sinpif((float)n1 * (1.0f / 128.0f));
        int n2 = (2 * tid + 65) & 127;           // odd
        float s2 = sinpif((float)n2 * (1.0f / 128.0f));
        const float sc = -(MPIF / 128.0f) / 16384.0f;
        h2o[tid] = make_float2(sc / (s1 * s1), sc / (s2 * s2));
    }
    int l = tid & 31, w = tid >> 5;
    int r = blockIdx.x * 8 + w;                  // row = t*1024 + s
    const float* row = feat + (size_t)r * 128;
    ps[w][l]      = row[l];
    ps[w][l + 32] = row[l + 32];
    ps[w][l + 64] = row[l + 64];
    ps[w][l + 96] = row[l + 96];
    __syncthreads();

    const float h0s = 0.25f * (MPIF / 128.0f);
    float e0 = ps[w][2 * l]      * h0s;
    float e1 = ps[w][2 * l + 64] * h0s;
    float o0 = ps[w][2 * l + 1]  * h0s;
    float o1 = ps[w][2 * l + 65] * h0s;

    float2 hcur = h2o[l];
    int idx = (l + 63) & 63;
#pragma unroll
    for (int m = 0; m < 64; m++) {
        float2 p2 = *(const float2*)&ps[w][2 * m];
        float2 ha = h2o[idx];
        o0 = fmaf(p2.x, hcur.x, o0);
        o1 = fmaf(p2.x, hcur.y, o1);
        e0 = fmaf(p2.y, ha.x, e0);
        e1 = fmaf(p2.y, ha.y, e1);
        hcur = ha;
        idx = (idx + 63) & 63;
    }

    __half* o = g_Fh + (size_t)r * 128;
    *(__half2*)(o + 2 * l)      = __floats2half2_rn(e0, o0);
    *(__half2*)(o + 2 * l + 64) = __floats2half2_rn(e1, o1);
}

// --------------------------- K2: weight build --------------------------------
__global__ __launch_bounds__(128) void k_wbuild() {
    __shared__ float sw[128 * 65];
    __shared__ float redn[128], redx[128];
    __shared__ float2 csang[16];
    int bid = blockIdx.x, tau = bid / NCH, ch = bid % NCH;
    int ilo = (ch == 0)  ? 8 : 0;
    int ihi = (ch == 16) ? 8 : 16;
    int p = threadIdx.x;
    if (p < 16) {
        int a = 8 * ch - 8 + p;
        float th = (float)a * (1.0f / 128.0f);
        csang[p] = make_float2(cospif(th), sinpif(th));
    }
    __syncthreads();

    int dx = p >> 4, dy = p & 15;
    float px = (float)((tau >> 3) * 8 + dx)  - 63.5f;
    float py = (float)((tau & 7) * 16 + dy) - 63.5f;

    float umin = 1e30f, umax = -1e30f;
    for (int i = ilo; i < ihi; i++) {
        float2 cs = csang[i];
        float u = px * cs.x + py * cs.y + 63.5f;
        umin = fminf(umin, u);
        umax = fmaxf(umax, u);
    }
    redn[p] = umin; redx[p] = umax; __syncthreads();
    for (int o = 64; o > 0; o >>= 1) {
        if (p < o) {
            redn[p] = fminf(redn[p], redn[p + o]);
            redx[p] = fmaxf(redx[p], redx[p + o]);
        }
        __syncthreads();
    }
    int lo = max(0, (int)floorf(redn[0]));
    int hi = min(127, (int)floorf(redx[0]) + 1);
    int base = max(0, min(64, lo - 2)) & ~7;
    int K16  = min(4, max(1, (hi + 1 - base + 15) >> 4));
    int kwid = K16 * 16;

    float* w64 = sw + p * 65;
    for (int k = 0; k < 64; k++) w64[k] = 0.f;
    for (int i = ilo; i < ihi; i++) {
        float cf = (i < 8) ? (float)i * 0.125f : 1.0f - (float)(i - 8) * 0.125f;
        float2 cs = csang[i];
        float u = px * cs.x + py * cs.y + 63.5f;
        float fl = floorf(u);
        int i0 = (int)fl;
        float fr = u - fl;
        int k0 = i0 - base;
        if (i0 >= 0 && i0 < 128 && k0 >= 0 && k0 < kwid)
            w64[k0] += cf * (1.0f - fr);
        int i1 = i0 + 1, k1 = k0 + 1;
        if (i1 >= 0 && i1 < 128 && k1 >= 0 && k1 < kwid)
            w64[k1] += cf * fr;
    }
    __half* Wp = g_W16 + (size_t)bid * 8192 + (size_t)p * 64;
#pragma unroll
    for (int k = 0; k < 64; k++) Wp[k] = __float2half_rn(w64[k]);
    if (p == 0) { g_base[bid] = base; g_kw[bid] = K16; }
}

// --------------------------- K3: GEMM (variable K) ---------------------------
static constexpr int SAW = 72;
static constexpr int STG = 2 * 128 * SAW;        // halves per stage (A+B)

extern __shared__ __half sm_g[];

__global__ __launch_bounds__(256, 2) void k_gemm(float* __restrict__ out) {
    __shared__ int s_base[NCH], s_kw[NCH];
    int tid = threadIdx.x;
    int tau = blockIdx.x >> 3;
    int s0  = (blockIdx.x & 7) * 128;
    int l = tid & 31, w = tid >> 5;
    int mw = w & 3, nw = w >> 2;
    int g = l >> 2, t4 = l & 3;

    if (tid < NCH) {
        s_base[tid] = g_base[tau * NCH + tid];
        s_kw[tid]   = g_kw[tau * NCH + tid];
    }
    __syncthreads();

    float c[2][8][4];
#pragma unroll
    for (int mt = 0; mt < 2; mt++)
#pragma unroll
        for (int nt = 0; nt < 8; nt++)
#pragma unroll
            for (int q = 0; q < 4; q++) c[mt][nt][q] = 0.f;

    // thread-per-row loader: tid<128 -> A row tid, else B row tid-128.
    auto issue_chunk = [&](int t, int stage) {
        int f = t & 15;                          // chunk 16 -> frame 0
        int base = s_base[t];
        int nv = 2 * s_kw[t];                    // uint4 vectors per row
        __half* As = sm_g + stage * STG;
        if (tid < 128) {
            const uint4* src = (const uint4*)(g_Fh + ((size_t)f * 1024 + s0 + tid) * 128 + base);
            __half* dst = As + tid * SAW;
            for (int j = 0; j < nv; j++) {
                unsigned da = (unsigned)__cvta_generic_to_shared(dst + j * 8);
                asm volatile("cp.async.cg.shared.global [%0], [%1], 16;"
                             :: "r"(da), "l"(src + j) : "memory");
            }
        } else {
            int row = tid - 128;
            const uint4* src = (const uint4*)(g_W16 + (size_t)(tau * NCH + t) * 8192
                                              + (size_t)row * 64);
            __half* dst = As + 128 * SAW + row * SAW;
            for (int j = 0; j < nv; j++) {
                unsigned da = (unsigned)__cvta_generic_to_shared(dst + j * 8);
                asm volatile("cp.async.cg.shared.global [%0], [%1], 16;"
                             :: "r"(da), "l"(src + j) : "memory");
            }
        }
        asm volatile("cp.async.commit_group;" ::: "memory");
    };

    issue_chunk(0, 0);

    for (int t = 0; t < NCH; t++) {
        if (t + 1 < NCH) {
            issue_chunk(t + 1, (t + 1) & 1);
            asm volatile("cp.async.wait_group 1;" ::: "memory");
        } else {
            asm volatile("cp.async.wait_group 0;" ::: "memory");
        }
        __syncthreads();

        const __half* As = sm_g + (t & 1) * STG;
        const __half* Bs = As + 128 * SAW;
        int kw = s_kw[t];
        for (int kk16 = 0; kk16 < kw; kk16++) {
            int kk = kk16 * 16;
            unsigned a[2][4];
#pragma unroll
            for (int mt = 0; mt < 2; mt++) {
                const __half* ar = &As[(mw * 32 + mt * 16 + g) * SAW + kk + t4 * 2];
                a[mt][0] = *(const unsigned*)ar;
                a[mt][1] = *(const unsigned*)(ar + 8 * SAW);
                a[mt][2] = *(const unsigned*)(ar + 8);
                a[mt][3] = *(const unsigned*)(ar + 8 * SAW + 8);
            }
#pragma unroll
            for (int nt = 0; nt < 8; nt++) {
                const __half* br = &Bs[(nw * 64 + nt * 8 + g) * SAW + kk + t4 * 2];
                unsigned b0 = *(const unsigned*)br;
                unsigned b1 = *(const unsigned*)(br + 8);
#pragma unroll
                for (int mt = 0; mt < 2; mt++) {
                    asm volatile(
                        "mma.sync.aligned.m16n8k16.row.col.f32.f16.f16.f32 "
                        "{%0,%1,%2,%3}, {%4,%5,%6,%7}, {%8,%9}, {%0,%1,%2,%3};"
                        : "+f"(c[mt][nt][0]), "+f"(c[mt][nt][1]),
                          "+f"(c[mt][nt][2]), "+f"(c[mt][nt][3])
                        : "r"(a[mt][0]), "r"(a[mt][1]),
                          "r"(a[mt][2]), "r"(a[mt][3]),
                          "r"(b0), "r"(b1));
                }
            }
        }
        __syncthreads();
    }

    int x0 = (tau >> 3) * 8, y0 = (tau & 7) * 16;
#pragma unroll
    for (int mt = 0; mt < 2; mt++) {
        int srow = s0 + mw * 32 + mt * 16 + g;
#pragma unroll
        for (int nt = 0; nt < 8; nt++) {
            int p = nw * 64 + nt * 8 + t4 * 2;
            int dx = p >> 4, dy = p & 15;
            size_t off = (size_t)srow * 16384 + (size_t)(x0 + dx) * 128 + (y0 + dy);
            *(float2*)(out + off) = make_float2(c[mt][nt][0], c[mt][nt][1]);
            *(float2*)(out + off + (size_t)8 * 16384) =
                make_float2(c[mt][nt][2], c[mt][nt][3]);
        }
    }
}

// ----------------------------------------------------------------------------
extern "C" void kernel_launch(void* const* d_in, const int* in_sizes, int n_in,
                              void* d_out, int out_size) {
    (void)in_sizes; (void)n_in; (void)out_size;
    const float* feat = (const float*)d_in[0];
    float* out = (float*)d_out;

    int smem_bytes = 2 * STG * (int)sizeof(__half);      // 73728
    cudaFuncSetAttribute(k_gemm, cudaFuncAttributeMaxDynamicSharedMemorySize,
                         smem_bytes);

    k_filter<<<2048, 256>>>(feat);
    k_wbuild<<<128 * NCH, 128>>>();
    k_gemm<<<1024, 256, smem_bytes>>>(out);
}

// round 17
// speedup vs baseline: 1.1503x; 1.1503x over previous
#include <cuda_runtime.h>
#include <cuda_fp16.h>

#define MPIF 3.14159265358979323846f

// ----------------------------------------------------------------------------
// FBP as banded GEMM on mma.sync (legacy-HMMA tensor rate ~68 T MAC/s).
//   K1 k_filter : ramp conv of 16 base frames -> fp16 (odd-tap parity split).
//   K2 k_wbuild : per (tile tau, K-chunk ch) banded weight rows, 17 chunks
//       (wrap split), per-chunk width K16 in {1..4}x16 from exact umin/umax.
//   K3 k_gemm   : D[128 s,128 p] = sum_ch A[s,16*K16]*B^T, m16n8k16, fp32
//       accum. Loader = proven fixed 8-vector spread (full 64-wide, overlap
//       hides it); MMA loop statically unrolled x4 with uniform early break
//       at kw -> keeps ptxas pipelining while skipping ~30% of the MACs.
// ----------------------------------------------------------------------------

static constexpr int NCH = 17;                   // K-chunks per tile

__device__ __half g_Fh[16 * 1024 * 128];         // filtered frames fp16, 4 MB
__device__ __half g_W16[128 * NCH * 128 * 64];   // weights [tau*17+ch][p][w], 34 MB
__device__ int    g_base[128 * NCH];             // band base col per (tau,ch)
__device__ int    g_kw[128 * NCH];               // band width /16 per (tau,ch)

// --------------------------- K1: filter (odd-tap) ----------------------------
__global__ __launch_bounds__(256) void k_filter(const float* __restrict__ feat) {
    __shared__ float2 h2o[64];
    __shared__ float  ps[8][128];
    int tid = threadIdx.x;
    if (tid < 64) {
        int n1 = 2 * tid + 1;
        float s1 = sinpif((float)n1 * (1.0f / 128.0f));
        int n2 = (2 * tid + 65) & 127;           // odd
        float s2 = sinpif((float)n2 * (1.0f / 128.0f));
        const float sc = -(MPIF / 128.0f) / 16384.0f;
        h2o[tid] = make_float2(sc / (s1 * s1), sc / (s2 * s2));
    }
    int l = tid & 31, w = tid >> 5;
    int r = blockIdx.x * 8 + w;                  // row = t*1024 + s
    const float* row = feat + (size_t)r * 128;
    ps[w][l]      = row[l];
    ps[w][l + 32] = row[l + 32];
    ps[w][l + 64] = row[l + 64];
    ps[w][l + 96] = row[l + 96];
    __syncthreads();

    const float h0s = 0.25f * (MPIF / 128.0f);
    float e0 = ps[w][2 * l]      * h0s;
    float e1 = ps[w][2 * l + 64] * h0s;
    float o0 = ps[w][2 * l + 1]  * h0s;
    float o1 = ps[w][2 * l + 65] * h0s;

    float2 hcur = h2o[l];
    int idx = (l + 63) & 63;
#pragma unroll
    for (int m = 0; m < 64; m++) {
        float2 p2 = *(const float2*)&ps[w][2 * m];
        float2 ha = h2o[idx];
        o0 = fmaf(p2.x, hcur.x, o0);
        o1 = fmaf(p2.x, hcur.y, o1);
        e0 = fmaf(p2.y, ha.x, e0);
        e1 = fmaf(p2.y, ha.y, e1);
        hcur = ha;
        idx = (idx + 63) & 63;
    }

    __half* o = g_Fh + (size_t)r * 128;
    *(__half2*)(o + 2 * l)      = __floats2half2_rn(e0, o0);
    *(__half2*)(o + 2 * l + 64) = __floats2half2_rn(e1, o1);
}

// --------------------------- K2: weight build --------------------------------
__global__ __launch_bounds__(128) void k_wbuild() {
    __shared__ float sw[128 * 65];
    __shared__ float redn[128], redx[128];
    __shared__ float2 csang[16];
    int bid = blockIdx.x, tau = bid / NCH, ch = bid % NCH;
    int ilo = (ch == 0)  ? 8 : 0;
    int ihi = (ch == 16) ? 8 : 16;
    int p = threadIdx.x;
    if (p < 16) {
        int a = 8 * ch - 8 + p;
        float th = (float)a * (1.0f / 128.0f);
        csang[p] = make_float2(cospif(th), sinpif(th));
    }
    __syncthreads();

    int dx = p >> 4, dy = p & 15;
    float px = (float)((tau >> 3) * 8 + dx)  - 63.5f;
    float py = (float)((tau & 7) * 16 + dy) - 63.5f;

    float umin = 1e30f, umax = -1e30f;
    for (int i = ilo; i < ihi; i++) {
        float2 cs = csang[i];
        float u = px * cs.x + py * cs.y + 63.5f;
        umin = fminf(umin, u);
        umax = fmaxf(umax, u);
    }
    redn[p] = umin; redx[p] = umax; __syncthreads();
    for (int o = 64; o > 0; o >>= 1) {
        if (p < o) {
            redn[p] = fminf(redn[p], redn[p + o]);
            redx[p] = fmaxf(redx[p], redx[p + o]);
        }
        __syncthreads();
    }
    int lo = max(0, (int)floorf(redn[0]));
    int hi = min(127, (int)floorf(redx[0]) + 1);
    int base = max(0, min(64, lo - 2)) & ~7;
    int K16  = min(4, max(1, (hi + 1 - base + 15) >> 4));
    int kwid = K16 * 16;

    float* w64 = sw + p * 65;
    for (int k = 0; k < 64; k++) w64[k] = 0.f;
    for (int i = ilo; i < ihi; i++) {
        float cf = (i < 8) ? (float)i * 0.125f : 1.0f - (float)(i - 8) * 0.125f;
        float2 cs = csang[i];
        float u = px * cs.x + py * cs.y + 63.5f;
        float fl = floorf(u);
        int i0 = (int)fl;
        float fr = u - fl;
        int k0 = i0 - base;
        if (i0 >= 0 && i0 < 128 && k0 >= 0 && k0 < kwid)
            w64[k0] += cf * (1.0f - fr);
        int i1 = i0 + 1, k1 = k0 + 1;
        if (i1 >= 0 && i1 < 128 && k1 >= 0 && k1 < kwid)
            w64[k1] += cf * fr;
    }
    __half* Wp = g_W16 + (size_t)bid * 8192 + (size_t)p * 64;
#pragma unroll
    for (int k = 0; k < 64; k++) Wp[k] = __float2half_rn(w64[k]);
    if (p == 0) { g_base[bid] = base; g_kw[bid] = K16; }
}

// --------------------------- K3: GEMM (variable K, static unroll) ------------
static constexpr int SAW = 72;
static constexpr int STG = 2 * 128 * SAW;        // halves per stage (A+B)

extern __shared__ __half sm_g[];

__global__ __launch_bounds__(256, 2) void k_gemm(float* __restrict__ out) {
    __shared__ int s_base[NCH], s_kw[NCH];
    int tid = threadIdx.x;
    int tau = blockIdx.x >> 3;
    int s0  = (blockIdx.x & 7) * 128;
    int l = tid & 31, w = tid >> 5;
    int mw = w & 3, nw = w >> 2;
    int g = l >> 2, t4 = l & 3;

    if (tid < NCH) {
        s_base[tid] = g_base[tau * NCH + tid];
        s_kw[tid]   = g_kw[tau * NCH + tid];
    }
    __syncthreads();

    float c[2][8][4];
#pragma unroll
    for (int mt = 0; mt < 2; mt++)
#pragma unroll
        for (int nt = 0; nt < 8; nt++)
#pragma unroll
            for (int q = 0; q < 4; q++) c[mt][nt][q] = 0.f;

    // proven fixed-spread loader: full 64-wide A+B (overlap hides the excess)
    auto issue_chunk = [&](int t, int stage) {
        int f = t & 15;                          // chunk 16 -> frame 0
        int base = s_base[t];
        const uint4* Ag = (const uint4*)(g_Fh + ((size_t)f * 1024 + s0) * 128 + base);
        const uint4* Bg = (const uint4*)(g_W16 + (size_t)(tau * NCH + t) * 8192);
        __half* As = sm_g + stage * STG;
        __half* Bs = As + 128 * SAW;
#pragma unroll
        for (int k = 0; k < 8; k++) {
            int c8 = tid + 256 * k;
            int row = (c8 >> 3) & 127;
            int j = c8 & 7;
            const uint4* src = (c8 < 1024) ? &Ag[row * 16 + j] : &Bg[row * 8 + j];
            __half* dst = ((c8 < 1024) ? As : Bs) + row * SAW + j * 8;
            unsigned da = (unsigned)__cvta_generic_to_shared(dst);
            asm volatile("cp.async.cg.shared.global [%0], [%1], 16;"
                         :: "r"(da), "l"(src) : "memory");
        }
        asm volatile("cp.async.commit_group;" ::: "memory");
    };

    issue_chunk(0, 0);

    for (int t = 0; t < NCH; t++) {
        if (t + 1 < NCH) {
            issue_chunk(t + 1, (t + 1) & 1);
            asm volatile("cp.async.wait_group 1;" ::: "memory");
        } else {
            asm volatile("cp.async.wait_group 0;" ::: "memory");
        }
        __syncthreads();

        const __half* As = sm_g + (t & 1) * STG;
        const __half* Bs = As + 128 * SAW;
        int kw = s_kw[t];
#pragma unroll
        for (int kk16 = 0; kk16 < 4; kk16++) {
            if (kk16 >= kw) break;               // block-uniform early exit
            int kk = kk16 * 16;
            unsigned a[2][4];
#pragma unroll
            for (int mt = 0; mt < 2; mt++) {
                const __half* ar = &As[(mw * 32 + mt * 16 + g) * SAW + kk + t4 * 2];
                a[mt][0] = *(const unsigned*)ar;
                a[mt][1] = *(const unsigned*)(ar + 8 * SAW);
                a[mt][2] = *(const unsigned*)(ar + 8);
                a[mt][3] = *(const unsigned*)(ar + 8 * SAW + 8);
            }
#pragma unroll
            for (int nt = 0; nt < 8; nt++) {
                const __half* br = &Bs[(nw * 64 + nt * 8 + g) * SAW + kk + t4 * 2];
                unsigned b0 = *(const unsigned*)br;
                unsigned b1 = *(const unsigned*)(br + 8);
#pragma unroll
                for (int mt = 0; mt < 2; mt++) {
                    asm volatile(
                        "mma.sync.aligned.m16n8k16.row.col.f32.f16.f16.f32 "
                        "{%0,%1,%2,%3}, {%4,%5,%6,%7}, {%8,%9}, {%0,%1,%2,%3};"
                        : "+f"(c[mt][nt][0]), "+f"(c[mt][nt][1]),
                          "+f"(c[mt][nt][2]), "+f"(c[mt][nt][3])
                        : "r"(a[mt][0]), "r"(a[mt][1]),
                          "r"(a[mt][2]), "r"(a[mt][3]),
                          "r"(b0), "r"(b1));
                }
            }
        }
        __syncthreads();
    }

    int x0 = (tau >> 3) * 8, y0 = (tau & 7) * 16;
#pragma unroll
    for (int mt = 0; mt < 2; mt++) {
        int srow = s0 + mw * 32 + mt * 16 + g;
#pragma unroll
        for (int nt = 0; nt < 8; nt++) {
            int p = nw * 64 + nt * 8 + t4 * 2;
            int dx = p >> 4, dy = p & 15;
            size_t off = (size_t)srow * 16384 + (size_t)(x0 + dx) * 128 + (y0 + dy);
            *(float2*)(out + off) = make_float2(c[mt][nt][0], c[mt][nt][1]);
            *(float2*)(out + off + (size_t)8 * 16384) =
                make_float2(c[mt][nt][2], c[mt][nt][3]);
        }
    }
}

// ----------------------------------------------------------------------------
extern "C" void kernel_launch(void* const* d_in, const int* in_sizes, int n_in,
                              void* d_out, int out_size) {
    (void)in_sizes; (void)n_in; (void)out_size;
    const float* feat = (const float*)d_in[0];
    float* out = (float*)d_out;

    int smem_bytes = 2 * STG * (int)sizeof(__half);      // 73728
    cudaFuncSetAttribute(k_gemm, cudaFuncAttributeMaxDynamicSharedMemorySize,
                         smem_bytes);

    k_filter<<<2048, 256>>>(feat);
    k_wbuild<<<128 * NCH, 128>>>();
    k_gemm<<<1024, 256, smem_bytes>>>(out);
}